// round 3
// baseline (speedup 1.0000x reference)
#include <cuda_runtime.h>
#include <cuda_bf16.h>
#include <math.h>

#define BB 64
#define LL 1024
#define HH 64
#define H2 128
#define VV 32000
#define TOK 128
#define HPAD 68

// Scratch (device globals; no allocation allowed)
__device__ float  g_kall[BB * LL * HH];   // 16 MB
__device__ float4 g_meta[BB * LL];        // (rinv, 0.16*kk, dot(k_t,k_{t+1}), 0)
__device__ float  g_r2[BB * HH];

// ---------------------------------------------------------------------------
// Kernel 1: per-token front-end (unchanged from round 2)
// ---------------------------------------------------------------------------
__global__ void __launch_bounds__(512) k1_frontend(
        const int* __restrict__ seq, const float* __restrict__ embed,
        const float* __restrict__ W1, const float* __restrict__ b1,
        const float* __restrict__ W2, const float* __restrict__ b2,
        const float* __restrict__ gamma, const float* __restrict__ beta,
        const float* __restrict__ kpW) {
    extern __shared__ float sm[];
    float* h_sm  = sm;                     // TOK * HPAD
    float* w1_sm = h_sm  + TOK * HPAD;     // 64*128
    float* u_sm  = w1_sm + HH * H2;        // 128*128
    float* w2_sm = u_sm  + TOK * H2;       // 128*64
    float* kp_sm = w2_sm + H2 * HH;        // 64*64
    float* b1s   = kp_sm + HH * HH;        // 128
    float* b2s   = b1s + H2;               // 64
    float* gsm   = b2s + HH;               // 64
    float* bsm   = gsm + HH;               // 64

    const int tid  = threadIdx.x;
    const int tok0 = blockIdx.x * TOK;

    for (int idx = tid; idx < HH * H2; idx += 512) w1_sm[idx] = W1[idx];
    for (int idx = tid; idx < H2 * HH; idx += 512) w2_sm[idx] = W2[idx];
    for (int idx = tid; idx < HH * HH; idx += 512) kp_sm[idx] = kpW[idx];
    if (tid < H2) b1s[tid] = b1[tid];
    if (tid < HH) { b2s[tid] = b2[tid]; gsm[tid] = gamma[tid]; bsm[tid] = beta[tid]; }

    #pragma unroll
    for (int k = 0; k < 16; k++) {
        int idx = tid + 512 * k;
        int t = idx >> 6, j = idx & 63;
        int row = seq[tok0 + t];
        h_sm[t * HPAD + j] = embed[row * HH + j];
    }
    __syncthreads();

    const int tt = tid >> 4;   // 0..31
    const int ct = tid & 15;   // 0..15

    // GEMM1: u = relu(h @ W1 + b1); 4 tok x 8 col per thread
    {
        const int r0 = tt * 4, c0 = ct * 8;
        float acc[4][8];
        #pragma unroll
        for (int r = 0; r < 4; r++)
            #pragma unroll
            for (int c = 0; c < 8; c++) acc[r][c] = 0.f;
        #pragma unroll 2
        for (int j4 = 0; j4 < HH; j4 += 4) {
            float hv[4][4];
            #pragma unroll
            for (int r = 0; r < 4; r++)
                *(float4*)hv[r] = *(const float4*)&h_sm[(r0 + r) * HPAD + j4];
            #pragma unroll
            for (int jj = 0; jj < 4; jj++) {
                float4 wA = *(const float4*)&w1_sm[(j4 + jj) * H2 + c0];
                float4 wB = *(const float4*)&w1_sm[(j4 + jj) * H2 + c0 + 4];
                #pragma unroll
                for (int r = 0; r < 4; r++) {
                    float hvv = hv[r][jj];
                    acc[r][0] = fmaf(hvv, wA.x, acc[r][0]);
                    acc[r][1] = fmaf(hvv, wA.y, acc[r][1]);
                    acc[r][2] = fmaf(hvv, wA.z, acc[r][2]);
                    acc[r][3] = fmaf(hvv, wA.w, acc[r][3]);
                    acc[r][4] = fmaf(hvv, wB.x, acc[r][4]);
                    acc[r][5] = fmaf(hvv, wB.y, acc[r][5]);
                    acc[r][6] = fmaf(hvv, wB.z, acc[r][6]);
                    acc[r][7] = fmaf(hvv, wB.w, acc[r][7]);
                }
            }
        }
        #pragma unroll
        for (int r = 0; r < 4; r++)
            #pragma unroll
            for (int c = 0; c < 8; c++)
                u_sm[(r0 + r) * H2 + c0 + c] = fmaxf(acc[r][c] + b1s[c0 + c], 0.f);
    }
    __syncthreads();

    // GEMM2 + residual
    {
        const int r0 = tt * 4, c0 = ct * 4;
        float acc[4][4];
        #pragma unroll
        for (int r = 0; r < 4; r++)
            #pragma unroll
            for (int c = 0; c < 4; c++) acc[r][c] = 0.f;
        #pragma unroll 2
        for (int j4 = 0; j4 < H2; j4 += 4) {
            float uv[4][4];
            #pragma unroll
            for (int r = 0; r < 4; r++)
                *(float4*)uv[r] = *(const float4*)&u_sm[(r0 + r) * H2 + j4];
            #pragma unroll
            for (int jj = 0; jj < 4; jj++) {
                float4 w = *(const float4*)&w2_sm[(j4 + jj) * HH + c0];
                #pragma unroll
                for (int r = 0; r < 4; r++) {
                    float uvv = uv[r][jj];
                    acc[r][0] = fmaf(uvv, w.x, acc[r][0]);
                    acc[r][1] = fmaf(uvv, w.y, acc[r][1]);
                    acc[r][2] = fmaf(uvv, w.z, acc[r][2]);
                    acc[r][3] = fmaf(uvv, w.w, acc[r][3]);
                }
            }
        }
        #pragma unroll
        for (int r = 0; r < 4; r++)
            #pragma unroll
            for (int c = 0; c < 4; c++)
                h_sm[(r0 + r) * HPAD + c0 + c] += acc[r][c] + b2s[c0 + c];
    }
    __syncthreads();

    // LayerNorm per token
    if (tid < TOK) {
        float s = 0.f, ss = 0.f;
        #pragma unroll 8
        for (int j = 0; j < HH; j++) {
            float x = h_sm[tid * HPAD + j];
            s += x; ss += x * x;
        }
        float mu = s * (1.f / HH);
        float var = ss * (1.f / HH) - mu * mu;
        float rs = rsqrtf(var + 1e-5f);
        #pragma unroll 8
        for (int j = 0; j < HH; j++) {
            float x = h_sm[tid * HPAD + j];
            h_sm[tid * HPAD + j] = (x - mu) * rs * gsm[j] + bsm[j];
        }
    }
    __syncthreads();

    // GEMM3: k = hn @ kpW -> g_kall
    {
        const int r0 = tt * 4, c0 = ct * 4;
        float acc[4][4];
        #pragma unroll
        for (int r = 0; r < 4; r++)
            #pragma unroll
            for (int c = 0; c < 4; c++) acc[r][c] = 0.f;
        #pragma unroll 2
        for (int j4 = 0; j4 < HH; j4 += 4) {
            float hv[4][4];
            #pragma unroll
            for (int r = 0; r < 4; r++)
                *(float4*)hv[r] = *(const float4*)&h_sm[(r0 + r) * HPAD + j4];
            #pragma unroll
            for (int jj = 0; jj < 4; jj++) {
                float4 w = *(const float4*)&kp_sm[(j4 + jj) * HH + c0];
                #pragma unroll
                for (int r = 0; r < 4; r++) {
                    float hvv = hv[r][jj];
                    acc[r][0] = fmaf(hvv, w.x, acc[r][0]);
                    acc[r][1] = fmaf(hvv, w.y, acc[r][1]);
                    acc[r][2] = fmaf(hvv, w.z, acc[r][2]);
                    acc[r][3] = fmaf(hvv, w.w, acc[r][3]);
                }
            }
        }
        #pragma unroll
        for (int r = 0; r < 4; r++)
            #pragma unroll
            for (int c = 0; c < 4; c++)
                g_kall[(tok0 + r0 + r) * HH + c0 + c] = acc[r][c];
    }
}

// ---------------------------------------------------------------------------
// Kernel 1b: per-(b,t) metadata: (rinv, 0.16*kk, dot(k_t,k_{t+1}))
// ---------------------------------------------------------------------------
__global__ void k1b_meta() {
    const int g    = blockIdx.x * 8 + (threadIdx.x >> 5);
    const int lane = threadIdx.x & 31;
    const int b = g >> 10, t = g & 1023;
    if (t >= LL - 1) return;
    const float* kt = g_kall + (b * LL + t) * HH;
    float2 k0 = *(const float2*)&kt[lane * 2];
    float2 k1 = *(const float2*)&kt[HH + lane * 2];
    float pkk = k0.x * k0.x + k0.y * k0.y;
    float pdt = k0.x * k1.x + k0.y * k1.y;
    #pragma unroll
    for (int off = 16; off; off >>= 1) {
        pkk += __shfl_xor_sync(0xffffffffu, pkk, off);
        pdt += __shfl_xor_sync(0xffffffffu, pdt, off);
    }
    if (lane == 0) {
        float rinv = 1.0f / fmaxf(sqrtf(pkk), 1e-12f);
        g_meta[b * LL + t] = make_float4(rinv, 0.16f * pkk, pdt, 0.f);
    }
}

// ---------------------------------------------------------------------------
// Kernel 2: sequential scan, 128 threads: thread (i = tid&63, h = tid>>6)
// owns M[i][h*32 .. h*32+31]. One-step deferred rank-1 update, single-chain
// err^2 gate reduction, ONE __syncthreads per step.
// ---------------------------------------------------------------------------
__global__ void __launch_bounds__(128, 1) k2_scan(const float* __restrict__ rpW,
                                                  const float* __restrict__ rpb) {
    const int b   = blockIdx.x;
    const int tid = threadIdx.x;
    const int i   = tid & 63;
    const int h   = tid >> 6;
    const int w   = tid >> 5;          // warp id 0..3

    __shared__ float kbuf[4][64];
    __shared__ float apart[2][2][64];  // [parity][h][i] : partial matvec
    __shared__ float wsum[2][2];       // [parity][low/high-i half] err^2 sums
    __shared__ float rds[64];

    float M[32];
    #pragma unroll
    for (int j = 0; j < 32; j++) M[j] = 0.f;

    const float*  kb = g_kall + b * LL * HH;
    const float4* mb = g_meta + b * LL;

    // init
    if (h == 0) {
        kbuf[0][i] = kb[i];
        kbuf[1][i] = kb[HH + i];
    }
    apart[0][h][i] = 0.f;
    float xA = 0.f, xB = 0.f;
    if (h == 0) { xA = kb[2 * HH + i]; xB = kb[3 * HH + i]; }
    float4 mt = mb[0];
    float gs_prev = 0.f, dot_prev = 0.f;
    int gate_prev = 0;
    __syncthreads();

    for (int t = 0; t < LL - 1; t++) {
        const int p = t & 1;
        float4 mtn = mb[t + 1];

        // 1. vpk_t (deferred correction) and err_t
        float vpk = apart[p][0][i] + apart[p][1][i];
        vpk = fmaf(gs_prev, dot_prev, vpk);
        float kc  = kbuf[t & 3][i];
        float err = fmaf(-mt.x, vpk, kc);        // k_i - rinv*vpk_i

        // 2. single-chain reduction of err^2 over this warp's 32 rows
        float perr = err * err;
        #pragma unroll
        for (int off = 16; off; off >>= 1)
            perr += __shfl_xor_sync(0xffffffffu, perr, off);
        if ((tid & 31) == 0) wsum[p][w & 1] = perr;   // warps 0/2 -> [0], 1/3 -> [1] (identical values)

        // 3. deferred update: M += gs_{t-1} * k^{t-1} (cols h*32..)
        if (gate_prev) {
            const float* kp = kbuf[(t + 3) & 3] + h * 32;
            #pragma unroll
            for (int j = 0; j < 32; j += 4) {
                float4 k4 = *(const float4*)&kp[j];
                M[j]     = fmaf(gs_prev, k4.x, M[j]);
                M[j + 1] = fmaf(gs_prev, k4.y, M[j + 1]);
                M[j + 2] = fmaf(gs_prev, k4.z, M[j + 2]);
                M[j + 3] = fmaf(gs_prev, k4.w, M[j + 3]);
            }
        }

        // 4. partial matvec for step t+1: a_part = M_{t-1}[i, hcols] . k^{t+1}
        {
            const float* kn = kbuf[(t + 1) & 3] + h * 32;
            float v0 = 0.f, v1 = 0.f, v2 = 0.f, v3 = 0.f;
            #pragma unroll
            for (int j = 0; j < 32; j += 4) {
                float4 k4 = *(const float4*)&kn[j];
                v0 = fmaf(M[j],     k4.x, v0);
                v1 = fmaf(M[j + 1], k4.y, v1);
                v2 = fmaf(M[j + 2], k4.z, v2);
                v3 = fmaf(M[j + 3], k4.w, v3);
            }
            apart[p ^ 1][h][i] = (v0 + v1) + (v2 + v3);
        }

        // 5. publish k^{t+2}, advance prefetch (h==0 threads)
        if (h == 0) {
            kbuf[(t + 2) & 3][i] = xA;
            xA = xB;
            xB = (t + 4 <= LL - 1) ? kb[(t + 4) * HH + i] : 0.f;
        }

        // 6. barrier, then finalize gate_t
        __syncthreads();
        float errsum = wsum[p][0] + wsum[p][1];
        int gate = errsum >= mt.y;                 // ||err||^2 >= 0.16*||k||^2
        gs_prev  = gate ? err * mt.x : 0.f;        // err_i * rinv
        gate_prev = gate;
        dot_prev = mt.z;
        mt = mtn;
    }

    // read = M_{L-2} @ q : partials in apart[(L-1)&1], last update via correction
    {
        const int pf = (LL - 1) & 1;
        float vq = apart[pf][0][i] + apart[pf][1][i];
        vq = fmaf(gs_prev, dot_prev, vq);
        if (h == 0) rds[i] = vq;
    }
    __syncthreads();

    // r2[b][i] = read . rpW[:, i] + rpb[i]  (split over h, merge via apart)
    {
        float acc = 0.f;
        #pragma unroll 8
        for (int j = 0; j < 32; j++)
            acc = fmaf(rds[h * 32 + j], rpW[(h * 32 + j) * HH + i], acc);
        apart[0][h][i] = acc;
    }
    __syncthreads();
    if (h == 0)
        g_r2[b * HH + i] = apart[0][0][i] + apart[0][1][i] + rpb[i];
}

// ---------------------------------------------------------------------------
// Kernel 3: out[b][v] = r2[b] . outW[:, v] + outb[v]
// 512 threads: 4 batch-groups x 128 v-lanes; 16 accumulators per thread.
// ---------------------------------------------------------------------------
__global__ void __launch_bounds__(512) k3_out(const float* __restrict__ outW,
                                              const float* __restrict__ outb,
                                              float* __restrict__ out) {
    __shared__ float r2s[64 * 64];
    const int tid = threadIdx.x;
    for (int idx = tid; idx < 64 * 64; idx += 512) r2s[idx] = g_r2[idx];
    __syncthreads();

    const int vl = tid & 127;
    const int g  = tid >> 7;           // batch group 0..3
    const int v  = blockIdx.x * 128 + vl;
    const int b0 = g * 16;

    float acc[16];
    #pragma unroll
    for (int bb = 0; bb < 16; bb++) acc[bb] = 0.f;

    #pragma unroll 8
    for (int j = 0; j < 64; j++) {
        float wv = outW[j * VV + v];
        #pragma unroll
        for (int bb = 0; bb < 16; bb++)
            acc[bb] = fmaf(r2s[(b0 + bb) * 64 + j], wv, acc[bb]);
    }
    float ob = outb[v];
    #pragma unroll
    for (int bb = 0; bb < 16; bb++) out[(b0 + bb) * VV + v] = acc[bb] + ob;
}

// ---------------------------------------------------------------------------
extern "C" void kernel_launch(void* const* d_in, const int* in_sizes, int n_in,
                              void* d_out, int out_size) {
    const int*   seq   = (const int*)d_in[0];
    const float* embed = (const float*)d_in[1];
    const float* W1    = (const float*)d_in[2];
    const float* b1    = (const float*)d_in[3];
    const float* W2    = (const float*)d_in[4];
    const float* b2    = (const float*)d_in[5];
    const float* gamma = (const float*)d_in[6];
    const float* beta  = (const float*)d_in[7];
    const float* kpW   = (const float*)d_in[8];
    const float* rpW   = (const float*)d_in[9];
    const float* rpb   = (const float*)d_in[10];
    const float* outW  = (const float*)d_in[11];
    const float* outb  = (const float*)d_in[12];
    float* out = (float*)d_out;

    const int smem1 = (TOK * HPAD + HH * H2 + TOK * H2 + H2 * HH + HH * HH
                       + H2 + 3 * HH) * (int)sizeof(float);
    cudaFuncSetAttribute(k1_frontend, cudaFuncAttributeMaxDynamicSharedMemorySize, smem1);

    k1_frontend<<<(BB * LL) / TOK, 512, smem1>>>(seq, embed, W1, b1, W2, b2,
                                                 gamma, beta, kpW);
    k1b_meta<<<(BB * LL) / 8, 256>>>();
    k2_scan<<<BB, 128>>>(rpW, rpb);
    k3_out<<<VV / 128, 512>>>(outW, outb, out);
}